// round 6
// baseline (speedup 1.0000x reference)
#include <cuda_runtime.h>
#include <stdint.h>

// Problem constants
#define BB 16
#define CC 4
#define HH 512
#define WW 1024
#define ROWS (BB * CC * HH)       // 32768
#define NBLK (ROWS / 8)           // 4096 blocks, 8 rows each
#define BCN  (BB * CC)            // 64 (b,c) groups; 64 blocks per group

// Per-(b,c) accumulators + completion counter. Zero-initialized at load;
// the last block resets them each launch so graph replays are clean.
__device__ float        g_err_acc[BCN];
__device__ float        g_cnt_acc[BCN];
__device__ unsigned int g_count = 0;

// ---------------------------------------------------------------------------
// Fused kernel: one warp per row, 8 rows per block (all in one (b,c) group).
//  Phase A: argmax over W=1024 of cls_true (first-max), gather the two
//    offsets at that index, mask by vertical, block-reduce 8 rows, then
//    RED.ADD (relaxed, no fence) into the per-group accumulator and bump a
//    counter with acq_rel semantics (encoded in the atomic — NO membar).
//  Phase B (last block only): acquire-read the 64 accumulator pairs from L2,
//    compute per-group means, write the scalar, reset state.
// ---------------------------------------------------------------------------
__global__ __launch_bounds__(256) void offset_loss_kernel(
    const float* __restrict__ offset_pred,
    const float* __restrict__ offset_true,
    const float* __restrict__ cls_true,
    const float* __restrict__ vertical_true,
    float* __restrict__ out)
{
    const int warp_in_block = threadIdx.x >> 5;
    const int lane = threadIdx.x & 31;
    const int row = blockIdx.x * 8 + warp_in_block;

    const float4* crow = reinterpret_cast<const float4*>(cls_true + (size_t)row * WW);

    // Front-batch all 8 coalesced float4 loads (512B/warp each) -> MLP 8.
    float4 v[8];
#pragma unroll
    for (int k = 0; k < 8; k++) {
        v[k] = __ldcs(&crow[k * 32 + lane]);   // streaming: read-once data
    }

    // Per-lane scan in increasing index order (first-max within lane).
    float best = -__int_as_float(0x7f800000);  // -inf
    int   bidx = 0;
#pragma unroll
    for (int k = 0; k < 8; k++) {
        const int base = (k * 32 + lane) * 4;
        if (v[k].x > best) { best = v[k].x; bidx = base + 0; }
        if (v[k].y > best) { best = v[k].y; bidx = base + 1; }
        if (v[k].z > best) { best = v[k].z; bidx = base + 2; }
        if (v[k].w > best) { best = v[k].w; bidx = base + 3; }
    }

    // Warp reduction: larger value wins; exact tie -> smaller index (first-max).
#pragma unroll
    for (int off = 16; off > 0; off >>= 1) {
        float oval = __shfl_xor_sync(0xffffffffu, best, off);
        int   oidx = __shfl_xor_sync(0xffffffffu, bidx, off);
        if (oval > best || (oval == best && oidx < bidx)) {
            best = oval;
            bidx = oidx;
        }
    }

    // Lane 0 of each warp: gather + mask for this row.
    __shared__ float s_err[8];
    __shared__ float s_cnt[8];
    __shared__ bool  s_last;
    if (lane == 0) {
        const size_t gidx = (size_t)row * WW + bidx;
        float p = __ldg(&offset_pred[gidx]);
        float t = __ldg(&offset_true[gidx]);
        float mask = (__ldg(&vertical_true[row]) >= 0.5f) ? 1.0f : 0.0f;
        s_err[warp_in_block] = fabsf(p - t) * mask;
        s_cnt[warp_in_block] = mask;
    }
    __syncthreads();

    // Warp 0, lanes 0..7 reduce the 8 row results; thread 0 accumulates into
    // the per-group slot (relaxed RED.ADD) and bumps the counter (acq_rel).
    if (threadIdx.x < 8) {
        float e = s_err[threadIdx.x];
        float c = s_cnt[threadIdx.x];
#pragma unroll
        for (int off = 4; off > 0; off >>= 1) {
            e += __shfl_xor_sync(0x000000ffu, e, off);
            c += __shfl_xor_sync(0x000000ffu, c, off);
        }
        if (threadIdx.x == 0) {
            const int bc = blockIdx.x >> 6;        // 64 blocks per group
            atomicAdd(&g_err_acc[bc], e);           // RED.ADD, relaxed, L2
            atomicAdd(&g_cnt_acc[bc], c);           // RED.ADD, relaxed, L2
            unsigned prev;
            asm volatile(
                "atom.acq_rel.gpu.global.add.u32 %0, [%1], 1;"
                : "=r"(prev) : "l"(&g_count) : "memory");
            s_last = (prev == (unsigned)(NBLK - 1));
        }
    }
    __syncthreads();
    if (!s_last) return;

    // ---- Phase B: last block only. All 4096 releases happened-before our
    // acquire; accumulators are final and L2-resident. ----
    const int t = threadIdx.x;

    float pbc = 0.0f;
    if (t < BCN) {
        float e, c;
        asm volatile("ld.acquire.gpu.global.f32 %0, [%1];"
                     : "=f"(e) : "l"(&g_err_acc[t]) : "memory");
        asm volatile("ld.acquire.gpu.global.f32 %0, [%1];"
                     : "=f"(c) : "l"(&g_cnt_acc[t]) : "memory");
        pbc = (c > 0.0f) ? (e / fmaxf(c, 1.0f)) : 0.0f;
        // Reset for next graph replay (flushed at kernel boundary).
        g_err_acc[t] = 0.0f;
        g_cnt_acc[t] = 0.0f;
    }
    if (t == 0) g_count = 0;

    // Reduce 64 pbc values held by threads 0..63 (warps 0 and 1).
    __shared__ float s_w[2];
#pragma unroll
    for (int off = 16; off > 0; off >>= 1) {
        pbc += __shfl_xor_sync(0xffffffffu, pbc, off);
    }
    if (t < BCN && (t & 31) == 0) s_w[t >> 5] = pbc;
    __syncthreads();

    if (t == 0) {
        out[0] = (s_w[0] + s_w[1]) / (float)BB;
    }
}

// ---------------------------------------------------------------------------
extern "C" void kernel_launch(void* const* d_in, const int* in_sizes, int n_in,
                              void* d_out, int out_size)
{
    const float* offset_pred   = (const float*)d_in[0];
    const float* offset_true   = (const float*)d_in[1];
    const float* cls_true      = (const float*)d_in[2];
    const float* vertical_true = (const float*)d_in[3];
    float* out = (float*)d_out;

    offset_loss_kernel<<<NBLK, 256>>>(offset_pred, offset_true, cls_true,
                                      vertical_true, out);
}

// round 7
// speedup vs baseline: 1.0744x; 1.0744x over previous
#include <cuda_runtime.h>
#include <stdint.h>

// Problem constants
#define BB 16
#define CC 4
#define HH 512
#define WW 1024
#define ROWS (BB * CC * HH)       // 32768
#define NBLK (ROWS / 8)           // 4096 blocks, 8 rows each
#define BCN  (BB * CC)            // 64 (b,c) groups; 64 blocks per group

// Per-(b,c) accumulators, padded to 128B stride to spread across L2 slices.
// [bc][0] = err sum, [bc][1] = cnt sum. Zero-initialized at module load; the
// finisher resets them after reading, so every graph replay sees zeros.
__device__ float g_acc[BCN][32];

// ---------------------------------------------------------------------------
// Kernel 1: one warp per row, 8 rows per block (all in one (b,c) group).
// Argmax over W=1024 of cls_true (first-max semantics), gather the offsets,
// apply vertical mask, block-reduce 8 rows, then two fire-and-forget RED.ADDs
// into the per-group accumulator. No with-return atomics, no extra barriers —
// block tail is identical to the proven streaming version.
// ---------------------------------------------------------------------------
__global__ __launch_bounds__(256) void row_argmax_kernel(
    const float* __restrict__ offset_pred,
    const float* __restrict__ offset_true,
    const float* __restrict__ cls_true,
    const float* __restrict__ vertical_true)
{
    const int warp_in_block = threadIdx.x >> 5;
    const int lane = threadIdx.x & 31;
    const int row = blockIdx.x * 8 + warp_in_block;

    const float4* crow = reinterpret_cast<const float4*>(cls_true + (size_t)row * WW);

    // Front-batch all 8 coalesced float4 loads (512B/warp each) -> MLP 8.
    float4 v[8];
#pragma unroll
    for (int k = 0; k < 8; k++) {
        v[k] = __ldcs(&crow[k * 32 + lane]);   // streaming: read-once data
    }

    // Per-lane scan in increasing index order (first-max within lane).
    float best = -__int_as_float(0x7f800000);  // -inf
    int   bidx = 0;
#pragma unroll
    for (int k = 0; k < 8; k++) {
        const int base = (k * 32 + lane) * 4;
        if (v[k].x > best) { best = v[k].x; bidx = base + 0; }
        if (v[k].y > best) { best = v[k].y; bidx = base + 1; }
        if (v[k].z > best) { best = v[k].z; bidx = base + 2; }
        if (v[k].w > best) { best = v[k].w; bidx = base + 3; }
    }

    // Warp reduction: larger value wins; exact tie -> smaller index (first-max).
#pragma unroll
    for (int off = 16; off > 0; off >>= 1) {
        float oval = __shfl_xor_sync(0xffffffffu, best, off);
        int   oidx = __shfl_xor_sync(0xffffffffu, bidx, off);
        if (oval > best || (oval == best && oidx < bidx)) {
            best = oval;
            bidx = oidx;
        }
    }

    // Lane 0 of each warp: gather + mask for this row.
    __shared__ float s_err[8];
    __shared__ float s_cnt[8];
    if (lane == 0) {
        const size_t gidx = (size_t)row * WW + bidx;
        float p = __ldg(&offset_pred[gidx]);
        float t = __ldg(&offset_true[gidx]);
        float mask = (__ldg(&vertical_true[row]) >= 0.5f) ? 1.0f : 0.0f;
        s_err[warp_in_block] = fabsf(p - t) * mask;
        s_cnt[warp_in_block] = mask;
    }
    __syncthreads();

    // Warp 0, lanes 0..7 reduce the 8 row results; thread 0 fires two REDs
    // (no return value -> REDG, no wait) and the block simply exits.
    if (threadIdx.x < 8) {
        float e = s_err[threadIdx.x];
        float c = s_cnt[threadIdx.x];
#pragma unroll
        for (int off = 4; off > 0; off >>= 1) {
            e += __shfl_xor_sync(0x000000ffu, e, off);
            c += __shfl_xor_sync(0x000000ffu, c, off);
        }
        if (threadIdx.x == 0) {
            const int bc = blockIdx.x >> 6;     // 64 blocks per group
            atomicAdd(&g_acc[bc][0], e);        // REDG.ADD (result unused)
            atomicAdd(&g_acc[bc][1], c);
        }
    }
}

// ---------------------------------------------------------------------------
// Kernel 2 (finisher, PDL secondary): 64 threads read the 64 accumulator
// pairs (8 KB, L2-hot), compute per-group means, reduce, write the scalar,
// and reset the accumulators for the next graph replay.
// ---------------------------------------------------------------------------
__global__ __launch_bounds__(64) void final_reduce_kernel(float* __restrict__ out)
{
#if __CUDA_ARCH__ >= 900
    cudaGridDependencySynchronize();
#endif

    const int t = threadIdx.x;   // 0..63

    float e = g_acc[t][0];
    float c = g_acc[t][1];
    float pbc = (c > 0.0f) ? (e / fmaxf(c, 1.0f)) : 0.0f;

    // Reset for the next replay (visible at kernel boundary).
    g_acc[t][0] = 0.0f;
    g_acc[t][1] = 0.0f;

    // Reduce 64 values across 2 warps.
    __shared__ float s_w[2];
#pragma unroll
    for (int off = 16; off > 0; off >>= 1) {
        pbc += __shfl_xor_sync(0xffffffffu, pbc, off);
    }
    if ((t & 31) == 0) s_w[t >> 5] = pbc;
    __syncthreads();

    if (t == 0) {
        out[0] = (s_w[0] + s_w[1]) / (float)BB;
    }
}

// ---------------------------------------------------------------------------
extern "C" void kernel_launch(void* const* d_in, const int* in_sizes, int n_in,
                              void* d_out, int out_size)
{
    const float* offset_pred   = (const float*)d_in[0];
    const float* offset_true   = (const float*)d_in[1];
    const float* cls_true      = (const float*)d_in[2];
    const float* vertical_true = (const float*)d_in[3];
    float* out = (float*)d_out;

    row_argmax_kernel<<<NBLK, 256>>>(offset_pred, offset_true, cls_true,
                                     vertical_true);

    // PDL launch of the finisher: overlaps its launch latency with the
    // primary kernel; device-side gridDependencySynchronize provides ordering.
    cudaLaunchAttribute attrs[1];
    attrs[0].id = cudaLaunchAttributeProgrammaticStreamSerialization;
    attrs[0].val.programmaticStreamSerializationAllowed = 1;

    cudaLaunchConfig_t cfg = {};
    cfg.gridDim = dim3(1, 1, 1);
    cfg.blockDim = dim3(64, 1, 1);
    cfg.dynamicSmemBytes = 0;
    cfg.stream = 0;
    cfg.attrs = attrs;
    cfg.numAttrs = 1;

    cudaLaunchKernelEx(&cfg, final_reduce_kernel, out);
}